// round 10
// baseline (speedup 1.0000x reference)
#include <cuda_runtime.h>
#include <math.h>

#define N_TOK 8192
#define K_CB  4096
#define DIM   256
#define Q_ELEMS (N_TOK * DIM)            // 2097152
#define OUT_IDX_OFF Q_ELEMS              // indices start
#define OUT_SCALAR_OFF (Q_ELEMS + N_TOK) // 6 scalars start
#define TIE_TAU 1e-6f                    // near-tie window: resolve to lowest index

// ---------------- scratch (device globals; no allocations) ----------------
__device__ float g_LN[N_TOK * DIM];   // normalized latent rows (fp32, IEEE division)
__device__ float g_CN[K_CB * DIM];    // normalized codebook rows
__device__ float g_sq[K_CB];          // raw ||codebook_k||^2
__device__ int   g_idx[N_TOK];
__device__ int   g_counts[K_CB];
__device__ double g_sel_sum;
__device__ double g_loss_sum;
__device__ double g_pair_sum;
__device__ unsigned int g_min_bits;

// ---------------- init: reset accumulators every launch ----------------
__global__ void init_kernel() {
    int t = blockIdx.x * blockDim.x + threadIdx.x;
    if (t < K_CB) g_counts[t] = 0;
    if (t == 0) {
        g_sel_sum  = 0.0;
        g_loss_sum = 0.0;
        g_pair_sum = 0.0;
        g_min_bits = 0x7f800000u;  // +inf
    }
}

// ---------------- row normalization (one warp per row), IEEE fp32 division -----------
__global__ void prep_kernel(const float* __restrict__ latent,
                            const float* __restrict__ cb) {
    int warp = (blockIdx.x * blockDim.x + threadIdx.x) >> 5;
    int lane = threadIdx.x & 31;
    if (warp >= N_TOK + K_CB) return;
    const float* src;
    float* dst;
    if (warp < N_TOK) { src = latent + (size_t)warp * DIM; dst = g_LN + (size_t)warp * DIM; }
    else              { src = cb + (size_t)(warp - N_TOK) * DIM; dst = g_CN + (size_t)(warp - N_TOK) * DIM; }
    float v[8];
    float ss = 0.f;
#pragma unroll
    for (int i = 0; i < 8; i++) { v[i] = src[lane + 32 * i]; ss += v[i] * v[i]; }
#pragma unroll
    for (int o = 16; o; o >>= 1) ss += __shfl_xor_sync(0xffffffffu, ss, o);
    if (warp >= N_TOK && lane == 0) g_sq[warp - N_TOK] = ss;  // raw sum-of-squares
    float nrm = fmaxf(sqrtf(ss), 1e-12f);                     // clip(norm, 1e-12)
#pragma unroll
    for (int i = 0; i < 8; i++) dst[lane + 32 * i] = __fdiv_rn(v[i], nrm);
}

// ------ GEMM 1: cosine = LN @ CN^T (fp32 in-order-k FFMA) + top-2 argmax w/ tie rule ----
// 128 blocks (64 rows each), 256 threads, 4x8 micro-tile, BN=128, BK=32
__global__ __launch_bounds__(256, 2) void cosine_argmax_kernel() {
    __shared__ __align__(16) float As[32][68];
    __shared__ __align__(16) float Bs[32][132];
    int tid = threadIdx.x;
    int ty = tid >> 4, tx = tid & 15;   // ty: 4-row group (0..15), tx: 8-col group (0..15)
    int m0 = blockIdx.x * 64;

    float tv1[4], tv2[4];
    int   ti1[4], ti2[4];
#pragma unroll
    for (int r = 0; r < 4; r++) { tv1[r] = -INFINITY; tv2[r] = -INFINITY; ti1[r] = 0; ti2[r] = 0; }

    for (int nt = 0; nt < K_CB / 128; nt++) {
        int n0 = nt * 128;
        float acc[4][8];
#pragma unroll
        for (int r = 0; r < 4; r++)
#pragma unroll
            for (int j = 0; j < 8; j++) acc[r][j] = 0.f;

        for (int dc = 0; dc < DIM; dc += 32) {
#pragma unroll
            for (int i = 0; i < 2; i++) {   // A: 64 rows x 8 float4 = 512 slots
                int s = tid + i * 256;
                int m = s >> 3, d4 = s & 7;
                float4 va = *(const float4*)&g_LN[(size_t)(m0 + m) * DIM + dc + d4 * 4];
                As[d4 * 4 + 0][m] = va.x; As[d4 * 4 + 1][m] = va.y;
                As[d4 * 4 + 2][m] = va.z; As[d4 * 4 + 3][m] = va.w;
            }
#pragma unroll
            for (int i = 0; i < 4; i++) {   // B: 128 rows x 8 float4 = 1024 slots
                int s = tid + i * 256;
                int m = s >> 3, d4 = s & 7;
                float4 vb = *(const float4*)&g_CN[(size_t)(n0 + m) * DIM + dc + d4 * 4];
                Bs[d4 * 4 + 0][m] = vb.x; Bs[d4 * 4 + 1][m] = vb.y;
                Bs[d4 * 4 + 2][m] = vb.z; Bs[d4 * 4 + 3][m] = vb.w;
            }
            __syncthreads();
#pragma unroll 8
            for (int dd = 0; dd < 32; dd++) {
                float4 a0 = *(const float4*)&As[dd][ty * 4];
                float4 b0 = *(const float4*)&Bs[dd][tx * 8];
                float4 b1 = *(const float4*)&Bs[dd][tx * 8 + 4];
                float a[4] = {a0.x, a0.y, a0.z, a0.w};
                float b[8] = {b0.x, b0.y, b0.z, b0.w, b1.x, b1.y, b1.z, b1.w};
#pragma unroll
                for (int r = 0; r < 4; r++)
#pragma unroll
                    for (int j = 0; j < 8; j++) acc[r][j] += a[r] * b[j];
            }
            __syncthreads();
        }
        // fold tile into running top-2 (ascending col index within thread)
#pragma unroll
        for (int r = 0; r < 4; r++)
#pragma unroll
            for (int j = 0; j < 8; j++) {
                float v = acc[r][j];
                int   i = n0 + tx * 8 + j;
                if (v > tv1[r]) { tv2[r] = tv1[r]; ti2[r] = ti1[r]; tv1[r] = v; ti1[r] = i; }
                else if (v > tv2[r]) { tv2[r] = v; ti2[r] = i; }
            }
    }

    int lane = tid & 31;
#pragma unroll
    for (int r = 0; r < 4; r++) {
        float v1 = tv1[r], v2 = tv2[r];
        int   i1 = ti1[r], i2 = ti2[r];
#pragma unroll
        for (int off = 8; off > 0; off >>= 1) {
            float w1 = __shfl_xor_sync(0xffffffffu, v1, off);
            int   j1 = __shfl_xor_sync(0xffffffffu, i1, off);
            float w2 = __shfl_xor_sync(0xffffffffu, v2, off);
            int   j2 = __shfl_xor_sync(0xffffffffu, i2, off);
            if (w1 > v1 || (w1 == v1 && j1 < i1)) {
                // w1 becomes best; second = better of (v1, w2)
                if (v1 > w2 || (v1 == w2 && i1 < j2)) { v2 = v1; i2 = i1; }
                else                                  { v2 = w2; i2 = j2; }
                v1 = w1; i1 = j1;
            } else {
                // v1 stays best; second = better of (v2, w1)  [w2 <= w1 can't beat it]
                if (w1 > v2 || (w1 == v2 && j1 < i2)) { v2 = w1; i2 = j1; }
            }
        }
        if ((lane & 15) == 0) {
            int row = m0 + ty * 4 + r;
            // near-tie: reference's softmax/argmax pipeline collapses sub-ulp gaps and
            // jnp.argmax resolves ties to the LOWEST index — emulate that.
            int ix = (v1 - v2 < TIE_TAU) ? min(i1, i2) : i1;
            g_idx[row] = ix;
        }
    }
}

// ---------------- GEMM 2: codebook pairwise distances (upper block-triangle) ----------------
__global__ __launch_bounds__(256, 2) void cdist_kernel(const float* __restrict__ cb) {
    __shared__ __align__(16) float As[32][132];
    __shared__ __align__(16) float Bs[32][132];
    __shared__ float s_sum[8];
    __shared__ float s_min[8];

    int rem = blockIdx.x, bi = 0;
    while (rem >= 32 - bi) { rem -= 32 - bi; bi++; }
    int bj = bi + rem;
    int i0 = bi * 128, j0 = bj * 128;

    int tid = threadIdx.x;
    int ty = tid >> 4, tx = tid & 15;

    float acc[8][8];
#pragma unroll
    for (int r = 0; r < 8; r++)
#pragma unroll
        for (int j = 0; j < 8; j++) acc[r][j] = 0.f;

    for (int dc = 0; dc < DIM; dc += 32) {
#pragma unroll
        for (int i = 0; i < 4; i++) {
            int s = tid + i * 256;
            int m = s >> 3, d4 = s & 7;
            float4 va = *(const float4*)&cb[(size_t)(i0 + m) * DIM + dc + d4 * 4];
            As[d4 * 4 + 0][m] = va.x; As[d4 * 4 + 1][m] = va.y;
            As[d4 * 4 + 2][m] = va.z; As[d4 * 4 + 3][m] = va.w;
            float4 vb = *(const float4*)&cb[(size_t)(j0 + m) * DIM + dc + d4 * 4];
            Bs[d4 * 4 + 0][m] = vb.x; Bs[d4 * 4 + 1][m] = vb.y;
            Bs[d4 * 4 + 2][m] = vb.z; Bs[d4 * 4 + 3][m] = vb.w;
        }
        __syncthreads();
#pragma unroll 8
        for (int dd = 0; dd < 32; dd++) {
            float4 a0 = *(const float4*)&As[dd][ty * 8];
            float4 a1 = *(const float4*)&As[dd][ty * 8 + 4];
            float4 b0 = *(const float4*)&Bs[dd][tx * 8];
            float4 b1 = *(const float4*)&Bs[dd][tx * 8 + 4];
            float a[8] = {a0.x, a0.y, a0.z, a0.w, a1.x, a1.y, a1.z, a1.w};
            float b[8] = {b0.x, b0.y, b0.z, b0.w, b1.x, b1.y, b1.z, b1.w};
#pragma unroll
            for (int r = 0; r < 8; r++)
#pragma unroll
                for (int j = 0; j < 8; j++) acc[r][j] += a[r] * b[j];
        }
        __syncthreads();
    }

    float sqi[8], sqj[8];
#pragma unroll
    for (int r = 0; r < 8; r++) sqi[r] = g_sq[i0 + ty * 8 + r];
#pragma unroll
    for (int j = 0; j < 8; j++) sqj[j] = g_sq[j0 + tx * 8 + j];

    float lsum = 0.f, lmin = INFINITY;
#pragma unroll
    for (int r = 0; r < 8; r++) {
        int gi = i0 + ty * 8 + r;
#pragma unroll
        for (int j = 0; j < 8; j++) {
            int gj = j0 + tx * 8 + j;
            float d2 = sqi[r] + sqj[j] - 2.f * acc[r][j];
            float dd = sqrtf(fmaxf(d2, 0.f));
            if (gi != gj) { lsum += dd; lmin = fminf(lmin, dd); }
        }
    }
    float w = (bi < bj) ? 2.f : 1.f;  // mirror blocks counted twice for the sum
    lsum *= w;

    int lane = tid & 31, wp = tid >> 5;
#pragma unroll
    for (int off = 16; off; off >>= 1) {
        lsum += __shfl_xor_sync(0xffffffffu, lsum, off);
        lmin = fminf(lmin, __shfl_xor_sync(0xffffffffu, lmin, off));
    }
    if (lane == 0) { s_sum[wp] = lsum; s_min[wp] = lmin; }
    __syncthreads();
    if (tid == 0) {
        float bs = 0.f, bm = INFINITY;
#pragma unroll
        for (int i = 0; i < 8; i++) { bs += s_sum[i]; bm = fminf(bm, s_min[i]); }
        atomicAdd(&g_pair_sum, (double)bs);
        atomicMin(&g_min_bits, __float_as_uint(bm));  // positive floats: uint order == float order
    }
}

// --------- gather quantized rows + loss + selected-cosine + counts + index output ---------
__global__ void gather_loss_kernel(const float* __restrict__ latent,
                                   const float* __restrict__ cb,
                                   float* __restrict__ out) {
    int n = blockIdx.x;
    int d = threadIdx.x;
    int ix = g_idx[n];
    float q = cb[(size_t)ix * DIM + d];
    out[(size_t)n * DIM + d] = q;
    float diff = latent[(size_t)n * DIM + d] - q;
    float s = diff * diff;
    float sc = g_LN[(size_t)n * DIM + d] * g_CN[(size_t)ix * DIM + d];
#pragma unroll
    for (int off = 16; off; off >>= 1) {
        s  += __shfl_xor_sync(0xffffffffu, s, off);
        sc += __shfl_xor_sync(0xffffffffu, sc, off);
    }
    __shared__ float sh[8];
    __shared__ float shc[8];
    int lane = d & 31, wp = d >> 5;
    if (lane == 0) { sh[wp] = s; shc[wp] = sc; }
    __syncthreads();
    if (d == 0) {
        float bs = 0.f, bc = 0.f;
#pragma unroll
        for (int i = 0; i < 8; i++) { bs += sh[i]; bc += shc[i]; }
        atomicAdd(&g_loss_sum, (double)bs);
        atomicAdd(&g_sel_sum, (double)bc);
        atomicAdd(&g_counts[ix], 1);
        out[OUT_IDX_OFF + n] = (float)ix;
    }
}

// ---------------- finalize scalars ----------------
__global__ void finalize_kernel(float* __restrict__ out) {
    __shared__ double sh[256];
    int t = threadIdx.x;
    double s = 0.0;
    for (int k = t; k < K_CB; k += 256) {
        double p = (double)g_counts[k] / (double)N_TOK;
        s += p * log(p + 1e-10);
    }
    sh[t] = s;
    __syncthreads();
    for (int off = 128; off; off >>= 1) {
        if (t < off) sh[t] += sh[t + off];
        __syncthreads();
    }
    if (t == 0) {
        double S = sh[0];
        double X = g_loss_sum / (double)Q_ELEMS;
        float* o = out + OUT_SCALAR_OFF;
        o[0] = (float)(0.25 * X);                         // commitment_loss
        o[1] = (float)X;                                  // codebook_loss
        o[2] = (float)exp(-S);                            // perplexity
        o[3] = (float)(g_sel_sum / (double)N_TOK);        // selected_cosine_sim
        o[4] = (float)(g_pair_sum / ((double)K_CB * (K_CB - 1)));  // avg_euclidean
        o[5] = __uint_as_float(g_min_bits);               // min_euclidean
    }
}

extern "C" void kernel_launch(void* const* d_in, const int* in_sizes, int n_in,
                              void* d_out, int out_size) {
    const float* latent = (const float*)d_in[0];
    const float* cb     = (const float*)d_in[1];
    // defensive: handle swapped metadata order
    if (n_in >= 2 && in_sizes[0] == K_CB * DIM && in_sizes[1] == N_TOK * DIM) {
        const float* t = latent; latent = cb; cb = t;
    }
    float* out = (float*)d_out;

    init_kernel<<<(K_CB + 255) / 256, 256>>>();
    prep_kernel<<<(N_TOK + K_CB) / 8, 256>>>(latent, cb);      // 1 warp/row
    cosine_argmax_kernel<<<N_TOK / 64, 256>>>();               // 128 blocks
    cdist_kernel<<<(32 * 33) / 2, 256>>>(cb);                  // 528 blocks
    gather_loss_kernel<<<N_TOK, 256>>>(latent, cb, out);
    finalize_kernel<<<1, 256>>>(out);
}

// round 12
// speedup vs baseline: 1.5631x; 1.5631x over previous
#include <cuda_runtime.h>
#include <math.h>

#define N_TOK 8192
#define K_CB  4096
#define DIM   256
#define Q_ELEMS (N_TOK * DIM)            // 2097152
#define OUT_IDX_OFF Q_ELEMS              // indices start
#define OUT_SCALAR_OFF (Q_ELEMS + N_TOK) // 6 scalars start
#define TIE_TAU 1e-6f                    // near-tie window: resolve to lowest index
#define NQ 4                             // codebook quarters for the cosine GEMM

typedef unsigned long long ull;

// ---------------- packed f32x2 helpers (Blackwell sm_103a) ----------------
__device__ __forceinline__ void ffma2(ull& d, ull a, ull b) {
    asm("fma.rn.f32x2 %0, %1, %2, %0;" : "+l"(d) : "l"(a), "l"(b));
}
__device__ __forceinline__ ull pack2(float lo, float hi) {
    ull r;
    asm("mov.b64 %0, {%1, %2};" : "=l"(r) : "f"(lo), "f"(hi));
    return r;
}
__device__ __forceinline__ void unpack2(float& lo, float& hi, ull p) {
    asm("mov.b64 {%0, %1}, %2;" : "=f"(lo), "=f"(hi) : "l"(p));
}

// ---------------- scratch (device globals; no allocations) ----------------
__device__ float g_LN[N_TOK * DIM];   // normalized latent rows (fp32, IEEE division)
__device__ float g_CN[K_CB * DIM];    // normalized codebook rows
__device__ float g_sq[K_CB];          // raw ||codebook_k||^2
__device__ int   g_idx[N_TOK];
__device__ int   g_counts[K_CB];
__device__ float g_pv1[N_TOK * NQ];   // per-quarter top-2 partials
__device__ float g_pv2[N_TOK * NQ];
__device__ int   g_pi1[N_TOK * NQ];
__device__ int   g_pi2[N_TOK * NQ];
__device__ double g_sel_sum;
__device__ double g_loss_sum;
__device__ double g_pair_sum;
__device__ unsigned int g_min_bits;

// ---------------- init: reset accumulators every launch ----------------
__global__ void init_kernel() {
    int t = blockIdx.x * blockDim.x + threadIdx.x;
    if (t < K_CB) g_counts[t] = 0;
    if (t == 0) {
        g_sel_sum  = 0.0;
        g_loss_sum = 0.0;
        g_pair_sum = 0.0;
        g_min_bits = 0x7f800000u;  // +inf
    }
}

// ---------------- row normalization (one warp per row), IEEE fp32 division -----------
__global__ void prep_kernel(const float* __restrict__ latent,
                            const float* __restrict__ cb) {
    int warp = (blockIdx.x * blockDim.x + threadIdx.x) >> 5;
    int lane = threadIdx.x & 31;
    if (warp >= N_TOK + K_CB) return;
    const float* src;
    float* dst;
    if (warp < N_TOK) { src = latent + (size_t)warp * DIM; dst = g_LN + (size_t)warp * DIM; }
    else              { src = cb + (size_t)(warp - N_TOK) * DIM; dst = g_CN + (size_t)(warp - N_TOK) * DIM; }
    float v[8];
    float ss = 0.f;
#pragma unroll
    for (int i = 0; i < 8; i++) { v[i] = src[lane + 32 * i]; ss += v[i] * v[i]; }
#pragma unroll
    for (int o = 16; o; o >>= 1) ss += __shfl_xor_sync(0xffffffffu, ss, o);
    if (warp >= N_TOK && lane == 0) g_sq[warp - N_TOK] = ss;  // raw sum-of-squares
    float nrm = fmaxf(sqrtf(ss), 1e-12f);                     // clip(norm, 1e-12)
#pragma unroll
    for (int i = 0; i < 8; i++) dst[lane + 32 * i] = __fdiv_rn(v[i], nrm);
}

// ------ GEMM 1: cosine = LN @ CN^T, fp32 serial-k via FFMA2, per-quarter top-2 -------
// grid 256 = 64 M-tiles x 4 codebook quarters; 256 threads; BM=128, BN=128, BK=32; 8x8 tile
__global__ __launch_bounds__(256, 2) void cosine_argmax_kernel() {
    __shared__ __align__(16) float As[32][132];
    __shared__ __align__(16) float Bs[32][132];
    int tid = threadIdx.x;
    int ty = tid >> 4, tx = tid & 15;
    int mt = blockIdx.x >> 2;           // M-tile (0..63)
    int q  = blockIdx.x & 3;            // codebook quarter (0..3)
    int m0 = mt * 128;

    float tv1[8], tv2[8];
    int   ti1[8], ti2[8];
#pragma unroll
    for (int r = 0; r < 8; r++) { tv1[r] = -INFINITY; tv2[r] = -INFINITY; ti1[r] = 0; ti2[r] = 0; }

    for (int nt = q * 8; nt < q * 8 + 8; nt++) {   // 8 N-tiles of 128 per quarter
        int n0 = nt * 128;
        ull acc2[8][4];
#pragma unroll
        for (int r = 0; r < 8; r++)
#pragma unroll
            for (int p = 0; p < 4; p++) acc2[r][p] = 0ull;

        for (int dc = 0; dc < DIM; dc += 32) {
#pragma unroll
            for (int i = 0; i < 4; i++) {
                int s = tid + i * 256;
                int m = s >> 3, d4 = s & 7;
                float4 va = *(const float4*)&g_LN[(size_t)(m0 + m) * DIM + dc + d4 * 4];
                As[d4 * 4 + 0][m] = va.x; As[d4 * 4 + 1][m] = va.y;
                As[d4 * 4 + 2][m] = va.z; As[d4 * 4 + 3][m] = va.w;
                float4 vb = *(const float4*)&g_CN[(size_t)(n0 + m) * DIM + dc + d4 * 4];
                Bs[d4 * 4 + 0][m] = vb.x; Bs[d4 * 4 + 1][m] = vb.y;
                Bs[d4 * 4 + 2][m] = vb.z; Bs[d4 * 4 + 3][m] = vb.w;
            }
            __syncthreads();
#pragma unroll 8
            for (int dd = 0; dd < 32; dd++) {
                float4 a0 = *(const float4*)&As[dd][ty * 8];
                float4 a1 = *(const float4*)&As[dd][ty * 8 + 4];
                ulonglong2 b01 = *(const ulonglong2*)&Bs[dd][tx * 8];
                ulonglong2 b23 = *(const ulonglong2*)&Bs[dd][tx * 8 + 4];
                ull bp[4] = {b01.x, b01.y, b23.x, b23.y};
                float ar[8] = {a0.x, a0.y, a0.z, a0.w, a1.x, a1.y, a1.z, a1.w};
#pragma unroll
                for (int r = 0; r < 8; r++) {
                    ull ap = pack2(ar[r], ar[r]);
#pragma unroll
                    for (int p = 0; p < 4; p++) ffma2(acc2[r][p], ap, bp[p]);
                }
            }
            __syncthreads();
        }
        // fold tile into running top-2 (ascending col index; lo lane = lower col)
#pragma unroll
        for (int r = 0; r < 8; r++)
#pragma unroll
            for (int p = 0; p < 4; p++) {
                float vlo, vhi;
                unpack2(vlo, vhi, acc2[r][p]);
                int ilo = n0 + tx * 8 + 2 * p;
                if (vlo > tv1[r]) { tv2[r] = tv1[r]; ti2[r] = ti1[r]; tv1[r] = vlo; ti1[r] = ilo; }
                else if (vlo > tv2[r]) { tv2[r] = vlo; ti2[r] = ilo; }
                if (vhi > tv1[r]) { tv2[r] = tv1[r]; ti2[r] = ti1[r]; tv1[r] = vhi; ti1[r] = ilo + 1; }
                else if (vhi > tv2[r]) { tv2[r] = vhi; ti2[r] = ilo + 1; }
            }
    }

    int lane = tid & 31;
#pragma unroll
    for (int r = 0; r < 8; r++) {
        float v1 = tv1[r], v2 = tv2[r];
        int   i1 = ti1[r], i2 = ti2[r];
#pragma unroll
        for (int off = 8; off > 0; off >>= 1) {
            float w1 = __shfl_xor_sync(0xffffffffu, v1, off);
            int   j1 = __shfl_xor_sync(0xffffffffu, i1, off);
            float w2 = __shfl_xor_sync(0xffffffffu, v2, off);
            int   j2 = __shfl_xor_sync(0xffffffffu, i2, off);
            if (w1 > v1 || (w1 == v1 && j1 < i1)) {
                if (v1 > w2 || (v1 == w2 && i1 < j2)) { v2 = v1; i2 = i1; }
                else                                  { v2 = w2; i2 = j2; }
                v1 = w1; i1 = j1;
            } else {
                if (w1 > v2 || (w1 == v2 && j1 < i2)) { v2 = w1; i2 = j1; }
            }
        }
        if ((lane & 15) == 0) {
            int row = m0 + ty * 8 + r;
            int o = row * NQ + q;
            g_pv1[o] = v1; g_pi1[o] = i1;
            g_pv2[o] = v2; g_pi2[o] = i2;
        }
    }
}

// ---------------- merge per-quarter top-2 partials + tie rule ----------------
__global__ void argmax_merge_kernel() {
    int row = blockIdx.x * blockDim.x + threadIdx.x;
    if (row >= N_TOK) return;
    float v1 = -INFINITY, v2 = -INFINITY;
    int i1 = 0, i2 = 0;
#pragma unroll
    for (int q = 0; q < NQ; q++) {
        int o = row * NQ + q;
        float w1 = g_pv1[o], w2 = g_pv2[o];
        int   j1 = g_pi1[o], j2 = g_pi2[o];
        // insert (w1, j1)
        if (w1 > v1 || (w1 == v1 && j1 < i1)) {
            v2 = v1; i2 = i1; v1 = w1; i1 = j1;
        } else if (w1 > v2 || (w1 == v2 && j1 < i2)) {
            v2 = w1; i2 = j1;
        }
        // insert (w2, j2)
        if (w2 > v1 || (w2 == v1 && j2 < i1)) {
            v2 = v1; i2 = i1; v1 = w2; i1 = j2;
        } else if (w2 > v2 || (w2 == v2 && j2 < i2)) {
            v2 = w2; i2 = j2;
        }
    }
    // near-tie: reference's softmax/argmax pipeline collapses sub-ulp gaps and
    // jnp.argmax resolves ties to the LOWEST index — emulate that.
    g_idx[row] = (v1 - v2 < TIE_TAU) ? min(i1, i2) : i1;
}

// ---------------- GEMM 2: codebook pairwise distances (upper block-triangle) ----------------
__global__ __launch_bounds__(256, 2) void cdist_kernel(const float* __restrict__ cb) {
    __shared__ __align__(16) float As[32][132];
    __shared__ __align__(16) float Bs[32][132];
    __shared__ float s_sum[8];
    __shared__ float s_min[8];

    int rem = blockIdx.x, bi = 0;
    while (rem >= 32 - bi) { rem -= 32 - bi; bi++; }
    int bj = bi + rem;
    int i0 = bi * 128, j0 = bj * 128;

    int tid = threadIdx.x;
    int ty = tid >> 4, tx = tid & 15;

    ull acc2[8][4];
#pragma unroll
    for (int r = 0; r < 8; r++)
#pragma unroll
        for (int p = 0; p < 4; p++) acc2[r][p] = 0ull;

    for (int dc = 0; dc < DIM; dc += 32) {
#pragma unroll
        for (int i = 0; i < 4; i++) {
            int s = tid + i * 256;
            int m = s >> 3, d4 = s & 7;
            float4 va = *(const float4*)&cb[(size_t)(i0 + m) * DIM + dc + d4 * 4];
            As[d4 * 4 + 0][m] = va.x; As[d4 * 4 + 1][m] = va.y;
            As[d4 * 4 + 2][m] = va.z; As[d4 * 4 + 3][m] = va.w;
            float4 vb = *(const float4*)&cb[(size_t)(j0 + m) * DIM + dc + d4 * 4];
            Bs[d4 * 4 + 0][m] = vb.x; Bs[d4 * 4 + 1][m] = vb.y;
            Bs[d4 * 4 + 2][m] = vb.z; Bs[d4 * 4 + 3][m] = vb.w;
        }
        __syncthreads();
#pragma unroll 8
        for (int dd = 0; dd < 32; dd++) {
            float4 a0 = *(const float4*)&As[dd][ty * 8];
            float4 a1 = *(const float4*)&As[dd][ty * 8 + 4];
            ulonglong2 b01 = *(const ulonglong2*)&Bs[dd][tx * 8];
            ulonglong2 b23 = *(const ulonglong2*)&Bs[dd][tx * 8 + 4];
            ull bp[4] = {b01.x, b01.y, b23.x, b23.y};
            float ar[8] = {a0.x, a0.y, a0.z, a0.w, a1.x, a1.y, a1.z, a1.w};
#pragma unroll
            for (int r = 0; r < 8; r++) {
                ull ap = pack2(ar[r], ar[r]);
#pragma unroll
                for (int p = 0; p < 4; p++) ffma2(acc2[r][p], ap, bp[p]);
            }
        }
        __syncthreads();
    }

    float sqi[8], sqj[8];
#pragma unroll
    for (int r = 0; r < 8; r++) sqi[r] = g_sq[i0 + ty * 8 + r];
#pragma unroll
    for (int j = 0; j < 8; j++) sqj[j] = g_sq[j0 + tx * 8 + j];

    float lsum = 0.f, lmin = INFINITY;
#pragma unroll
    for (int r = 0; r < 8; r++) {
        int gi = i0 + ty * 8 + r;
#pragma unroll
        for (int p = 0; p < 4; p++) {
            float alo, ahi;
            unpack2(alo, ahi, acc2[r][p]);
            int gj = j0 + tx * 8 + 2 * p;
            float d2a = sqi[r] + sqj[2 * p]     - 2.f * alo;
            float d2b = sqi[r] + sqj[2 * p + 1] - 2.f * ahi;
            float da = sqrtf(fmaxf(d2a, 0.f));
            float db = sqrtf(fmaxf(d2b, 0.f));
            if (gi != gj)     { lsum += da; lmin = fminf(lmin, da); }
            if (gi != gj + 1) { lsum += db; lmin = fminf(lmin, db); }
        }
    }
    float w = (bi < bj) ? 2.f : 1.f;  // mirror blocks counted twice for the sum
    lsum *= w;

    int lane = tid & 31, wp = tid >> 5;
#pragma unroll
    for (int off = 16; off; off >>= 1) {
        lsum += __shfl_xor_sync(0xffffffffu, lsum, off);
        lmin = fminf(lmin, __shfl_xor_sync(0xffffffffu, lmin, off));
    }
    if (lane == 0) { s_sum[wp] = lsum; s_min[wp] = lmin; }
    __syncthreads();
    if (tid == 0) {
        float bs = 0.f, bm = INFINITY;
#pragma unroll
        for (int i = 0; i < 8; i++) { bs += s_sum[i]; bm = fminf(bm, s_min[i]); }
        atomicAdd(&g_pair_sum, (double)bs);
        atomicMin(&g_min_bits, __float_as_uint(bm));  // positive floats: uint order == float order
    }
}

// --------- gather quantized rows + loss + selected-cosine + counts + index output ---------
__global__ void gather_loss_kernel(const float* __restrict__ latent,
                                   const float* __restrict__ cb,
                                   float* __restrict__ out) {
    int n = blockIdx.x;
    int d = threadIdx.x;
    int ix = g_idx[n];
    float q = cb[(size_t)ix * DIM + d];
    out[(size_t)n * DIM + d] = q;
    float diff = latent[(size_t)n * DIM + d] - q;
    float s = diff * diff;
    float sc = g_LN[(size_t)n * DIM + d] * g_CN[(size_t)ix * DIM + d];
#pragma unroll
    for (int off = 16; off; off >>= 1) {
        s  += __shfl_xor_sync(0xffffffffu, s, off);
        sc += __shfl_xor_sync(0xffffffffu, sc, off);
    }
    __shared__ float sh[8];
    __shared__ float shc[8];
    int lane = d & 31, wp = d >> 5;
    if (lane == 0) { sh[wp] = s; shc[wp] = sc; }
    __syncthreads();
    if (d == 0) {
        float bs = 0.f, bc = 0.f;
#pragma unroll
        for (int i = 0; i < 8; i++) { bs += sh[i]; bc += shc[i]; }
        atomicAdd(&g_loss_sum, (double)bs);
        atomicAdd(&g_sel_sum, (double)bc);
        atomicAdd(&g_counts[ix], 1);
        out[OUT_IDX_OFF + n] = (float)ix;
    }
}

// ---------------- finalize scalars ----------------
__global__ void finalize_kernel(float* __restrict__ out) {
    __shared__ double sh[256];
    int t = threadIdx.x;
    double s = 0.0;
    for (int k = t; k < K_CB; k += 256) {
        double p = (double)g_counts[k] / (double)N_TOK;
        s += p * log(p + 1e-10);
    }
    sh[t] = s;
    __syncthreads();
    for (int off = 128; off; off >>= 1) {
        if (t < off) sh[t] += sh[t + off];
        __syncthreads();
    }
    if (t == 0) {
        double S = sh[0];
        double X = g_loss_sum / (double)Q_ELEMS;
        float* o = out + OUT_SCALAR_OFF;
        o[0] = (float)(0.25 * X);                         // commitment_loss
        o[1] = (float)X;                                  // codebook_loss
        o[2] = (float)exp(-S);                            // perplexity
        o[3] = (float)(g_sel_sum / (double)N_TOK);        // selected_cosine_sim
        o[4] = (float)(g_pair_sum / ((double)K_CB * (K_CB - 1)));  // avg_euclidean
        o[5] = __uint_as_float(g_min_bits);               // min_euclidean
    }
}

extern "C" void kernel_launch(void* const* d_in, const int* in_sizes, int n_in,
                              void* d_out, int out_size) {
    const float* latent = (const float*)d_in[0];
    const float* cb     = (const float*)d_in[1];
    // defensive: handle swapped metadata order
    if (n_in >= 2 && in_sizes[0] == K_CB * DIM && in_sizes[1] == N_TOK * DIM) {
        const float* t = latent; latent = cb; cb = t;
    }
    float* out = (float*)d_out;

    init_kernel<<<(K_CB + 255) / 256, 256>>>();
    prep_kernel<<<(N_TOK + K_CB) / 8, 256>>>(latent, cb);      // 1 warp/row
    cosine_argmax_kernel<<<64 * NQ, 256>>>();                  // 256 blocks
    argmax_merge_kernel<<<N_TOK / 256, 256>>>();               // merge quarters + tie rule
    cdist_kernel<<<(32 * 33) / 2, 256>>>(cb);                  // 528 blocks
    gather_loss_kernel<<<N_TOK, 256>>>(latent, cb, out);
    finalize_kernel<<<1, 256>>>(out);
}

// round 14
// speedup vs baseline: 2.0658x; 1.3216x over previous
#include <cuda_runtime.h>
#include <cuda_bf16.h>
#include <math.h>
#include <stdint.h>

#define N_TOK 8192
#define K_CB  4096
#define DIM   256
#define Q_ELEMS (N_TOK * DIM)            // 2097152
#define OUT_IDX_OFF Q_ELEMS              // indices start
#define OUT_SCALAR_OFF (Q_ELEMS + N_TOK) // 6 scalars start
#define TIE_TAU 1e-6f                    // near-tie window: resolve to lowest index
#define NQ 32                            // N-tiles of 128 in the cosine GEMM

typedef unsigned long long ull;

// ---------------- packed f32x2 helpers (Blackwell sm_103) ----------------
__device__ __forceinline__ void ffma2(ull& d, ull a, ull b) {
    asm("fma.rn.f32x2 %0, %1, %2, %0;" : "+l"(d) : "l"(a), "l"(b));
}
__device__ __forceinline__ ull pack2(float lo, float hi) {
    ull r;
    asm("mov.b64 %0, {%1, %2};" : "=l"(r) : "f"(lo), "f"(hi));
    return r;
}
__device__ __forceinline__ void unpack2(float& lo, float& hi, ull p) {
    asm("mov.b64 {%0, %1}, %2;" : "=f"(lo), "=f"(hi) : "l"(p));
}

// ---------------- scratch (device globals; no allocations) ----------------
__device__ float g_LN[N_TOK * DIM];   // normalized latent rows (fp32, IEEE division)
__device__ float g_CN[K_CB * DIM];    // normalized codebook rows
__device__ __nv_bfloat16 g_LNhi[N_TOK * DIM];
__device__ __nv_bfloat16 g_LNlo[N_TOK * DIM];
__device__ __nv_bfloat16 g_CNhi[K_CB * DIM];
__device__ __nv_bfloat16 g_CNlo[K_CB * DIM];
__device__ float g_sq[K_CB];          // raw ||codebook_k||^2
__device__ int   g_idx[N_TOK];
__device__ int   g_counts[K_CB];
__device__ float g_pv1[N_TOK * NQ];   // per-N-tile top-2 partials
__device__ float g_pv2[N_TOK * NQ];
__device__ int   g_pi1[N_TOK * NQ];
__device__ int   g_pi2[N_TOK * NQ];
__device__ double g_sel_sum;
__device__ double g_loss_sum;
__device__ double g_pair_sum;
__device__ unsigned int g_min_bits;

// ---------------- init: reset accumulators every launch ----------------
__global__ void init_kernel() {
    int t = blockIdx.x * blockDim.x + threadIdx.x;
    if (t < K_CB) g_counts[t] = 0;
    if (t == 0) {
        g_sel_sum  = 0.0;
        g_loss_sum = 0.0;
        g_pair_sum = 0.0;
        g_min_bits = 0x7f800000u;  // +inf
    }
}

// ------- row normalization + bf16 hi/lo split (one warp per row), IEEE division -------
__global__ void prep_kernel(const float* __restrict__ latent,
                            const float* __restrict__ cb) {
    int warp = (blockIdx.x * blockDim.x + threadIdx.x) >> 5;
    int lane = threadIdx.x & 31;
    if (warp >= N_TOK + K_CB) return;
    const float* src;
    float* dst;
    __nv_bfloat16 *dhi, *dlo;
    size_t off;
    if (warp < N_TOK) {
        off = (size_t)warp * DIM;
        src = latent + off; dst = g_LN + off; dhi = g_LNhi + off; dlo = g_LNlo + off;
    } else {
        off = (size_t)(warp - N_TOK) * DIM;
        src = cb + off; dst = g_CN + off; dhi = g_CNhi + off; dlo = g_CNlo + off;
    }
    float v[8];
    float ss = 0.f;
#pragma unroll
    for (int i = 0; i < 8; i++) { v[i] = src[lane + 32 * i]; ss += v[i] * v[i]; }
#pragma unroll
    for (int o = 16; o; o >>= 1) ss += __shfl_xor_sync(0xffffffffu, ss, o);
    if (warp >= N_TOK && lane == 0) g_sq[warp - N_TOK] = ss;  // raw sum-of-squares
    float nrm = fmaxf(sqrtf(ss), 1e-12f);                     // clip(norm, 1e-12)
#pragma unroll
    for (int i = 0; i < 8; i++) {
        float x = __fdiv_rn(v[i], nrm);
        dst[lane + 32 * i] = x;
        __nv_bfloat16 h = __float2bfloat16_rn(x);
        dhi[lane + 32 * i] = h;
        dlo[lane + 32 * i] = __float2bfloat16_rn(x - __bfloat162float(h));
    }
}

// ---- GEMM 1: cosine via mma.sync bf16 split (hi*hi + hi*lo + lo*hi), fp32 accum ----
// grid 2048 = 64 M-tiles x 32 N-tiles; 256 thr; BM=BN=128, BK=64; warps 2x4, tile 64x32
#define APITCH 72   // bf16 per SMEM row (64 data + 8 pad) = 36 words
#define T_BYTES (128 * APITCH * 2)   // 18432
struct TopEnt { float v1, v2; int i1, i2; };

__device__ __forceinline__ void top2_ins(float& v1, int& i1, float& v2, int& i2,
                                         float w, int j) {
    if (w > v1 || (w == v1 && j < i1)) { v2 = v1; i2 = i1; v1 = w; i1 = j; }
    else if (w > v2 || (w == v2 && j < i2)) { v2 = w; i2 = j; }
}

__global__ __launch_bounds__(256) void cosine_mma_kernel() {
    extern __shared__ __align__(16) char smem[];
    uint32_t* sAhi = (uint32_t*)(smem);
    uint32_t* sAlo = (uint32_t*)(smem + T_BYTES);
    uint32_t* sBhi = (uint32_t*)(smem + 2 * T_BYTES);
    uint32_t* sBlo = (uint32_t*)(smem + 3 * T_BYTES);

    int tid = threadIdx.x;
    int wid = tid >> 5, lane = tid & 31;
    int wm = wid >> 2, wn = wid & 3;
    int tq = lane >> 2, tr = lane & 3;

    int nt = blockIdx.x & 31, mt = blockIdx.x >> 5;
    int m0 = mt * 128, n0 = nt * 128;

    float acc[4][4][4];
#pragma unroll
    for (int mi = 0; mi < 4; mi++)
#pragma unroll
        for (int ni = 0; ni < 4; ni++)
#pragma unroll
            for (int c = 0; c < 4; c++) acc[mi][ni][c] = 0.f;

    const ushort* LNhi = (const ushort*)g_LNhi;
    const ushort* LNlo = (const ushort*)g_LNlo;
    const ushort* CNhi = (const ushort*)g_CNhi;
    const ushort* CNlo = (const ushort*)g_CNlo;

    for (int kc = 0; kc < 4; kc++) {
        int dc = kc * 64;
        __syncthreads();   // previous chunk's reads done before overwrite
#pragma unroll
        for (int i = 0; i < 4; i++) {
            int s = tid + i * 256;           // 0..1023 slots of 8 bf16
            int m = s >> 3, c8 = (s & 7) * 8;
            int so = m * APITCH + c8;        // bf16 units
            size_t ga = (size_t)(m0 + m) * DIM + dc + c8;
            size_t gb = (size_t)(n0 + m) * DIM + dc + c8;
            *(uint4*)((char*)sAhi + so * 2) = *(const uint4*)&LNhi[ga];
            *(uint4*)((char*)sAlo + so * 2) = *(const uint4*)&LNlo[ga];
            *(uint4*)((char*)sBhi + so * 2) = *(const uint4*)&CNhi[gb];
            *(uint4*)((char*)sBlo + so * 2) = *(const uint4*)&CNlo[gb];
        }
        __syncthreads();
#pragma unroll
        for (int pass = 0; pass < 3; pass++) {
            const uint32_t* A = (pass == 2) ? sAlo : sAhi;
            const uint32_t* B = (pass == 1) ? sBlo : sBhi;
#pragma unroll
            for (int ks = 0; ks < 4; ks++) {
                uint32_t a[4][4];
#pragma unroll
                for (int mi = 0; mi < 4; mi++) {
                    int w = (wm * 64 + mi * 16 + tq) * 36 + ks * 8 + tr;
                    a[mi][0] = A[w];
                    a[mi][1] = A[w + 8 * 36];
                    a[mi][2] = A[w + 4];
                    a[mi][3] = A[w + 8 * 36 + 4];
                }
#pragma unroll
                for (int ni = 0; ni < 4; ni++) {
                    int w = (wn * 32 + ni * 8 + tq) * 36 + ks * 8 + tr;
                    uint32_t b0 = B[w], b1 = B[w + 4];
#pragma unroll
                    for (int mi = 0; mi < 4; mi++) {
                        asm("mma.sync.aligned.m16n8k16.row.col.f32.bf16.bf16.f32 "
                            "{%0,%1,%2,%3}, {%4,%5,%6,%7}, {%8,%9}, {%0,%1,%2,%3};"
                            : "+f"(acc[mi][ni][0]), "+f"(acc[mi][ni][1]),
                              "+f"(acc[mi][ni][2]), "+f"(acc[mi][ni][3])
                            : "r"(a[mi][0]), "r"(a[mi][1]), "r"(a[mi][2]), "r"(a[mi][3]),
                              "r"(b0), "r"(b1));
                    }
                }
            }
        }
    }
    __syncthreads();   // tiles no longer needed; reuse smem for epilogue

    // epilogue: lane holds rows (wm*64 + mi*16 + tq + 8h), cols (wn*32 + ni*8 + tr*2 + {0,1})
    TopEnt* ebuf = (TopEnt*)smem;   // [128 rows][4 wn] = 512 entries, 8KB
#pragma unroll
    for (int mi = 0; mi < 4; mi++)
#pragma unroll
        for (int h = 0; h < 2; h++) {
            float v1 = -INFINITY, v2 = -INFINITY;
            int i1 = 0, i2 = 0;
#pragma unroll
            for (int ni = 0; ni < 4; ni++) {   // ascending cols within lane
                int col = n0 + wn * 32 + ni * 8 + tr * 2;
                top2_ins(v1, i1, v2, i2, acc[mi][ni][h * 2], col);
                top2_ins(v1, i1, v2, i2, acc[mi][ni][h * 2 + 1], col + 1);
            }
#pragma unroll
            for (int off = 1; off <= 2; off <<= 1) {   // quad merge (same rows)
                float w1 = __shfl_xor_sync(0xffffffffu, v1, off);
                int   j1 = __shfl_xor_sync(0xffffffffu, i1, off);
                float w2 = __shfl_xor_sync(0xffffffffu, v2, off);
                int   j2 = __shfl_xor_sync(0xffffffffu, i2, off);
                top2_ins(v1, i1, v2, i2, w1, j1);
                top2_ins(v1, i1, v2, i2, w2, j2);
            }
            if (tr == 0) {
                int rit = wm * 64 + mi * 16 + tq + h * 8;
                TopEnt e; e.v1 = v1; e.v2 = v2; e.i1 = i1; e.i2 = i2;
                ebuf[rit * 4 + wn] = e;
            }
        }
    __syncthreads();
    if (tid < 128) {
        float v1 = -INFINITY, v2 = -INFINITY;
        int i1 = 0, i2 = 0;
#pragma unroll
        for (int w = 0; w < 4; w++) {   // ascending col ranges
            TopEnt e = ebuf[tid * 4 + w];
            top2_ins(v1, i1, v2, i2, e.v1, e.i1);
            top2_ins(v1, i1, v2, i2, e.v2, e.i2);
        }
        int o = (m0 + tid) * NQ + nt;
        g_pv1[o] = v1; g_pi1[o] = i1;
        g_pv2[o] = v2; g_pi2[o] = i2;
    }
}

// ---------------- merge per-N-tile top-2 partials + tie rule ----------------
__global__ void argmax_merge_kernel() {
    int row = blockIdx.x * blockDim.x + threadIdx.x;
    if (row >= N_TOK) return;
    float v1 = -INFINITY, v2 = -INFINITY;
    int i1 = 0, i2 = 0;
    for (int q = 0; q < NQ; q++) {      // ascending column ranges
        int o = row * NQ + q;
        top2_ins(v1, i1, v2, i2, g_pv1[o], g_pi1[o]);
        top2_ins(v1, i1, v2, i2, g_pv2[o], g_pi2[o]);
    }
    // near-tie: reference's softmax/argmax pipeline collapses sub-ulp gaps and
    // jnp.argmax resolves ties to the LOWEST index — emulate that.
    g_idx[row] = (v1 - v2 < TIE_TAU) ? min(i1, i2) : i1;
}

// ---------------- GEMM 2: codebook pairwise distances (upper block-triangle) ----------------
__global__ __launch_bounds__(256, 2) void cdist_kernel(const float* __restrict__ cb) {
    __shared__ __align__(16) float As[32][132];
    __shared__ __align__(16) float Bs[32][132];
    __shared__ float s_sum[8];
    __shared__ float s_min[8];

    int rem = blockIdx.x, bi = 0;
    while (rem >= 32 - bi) { rem -= 32 - bi; bi++; }
    int bj = bi + rem;
    int i0 = bi * 128, j0 = bj * 128;

    int tid = threadIdx.x;
    int ty = tid >> 4, tx = tid & 15;

    ull acc2[8][4];
#pragma unroll
    for (int r = 0; r < 8; r++)
#pragma unroll
        for (int p = 0; p < 4; p++) acc2[r][p] = 0ull;

    for (int dc = 0; dc < DIM; dc += 32) {
#pragma unroll
        for (int i = 0; i < 4; i++) {
            int s = tid + i * 256;
            int m = s >> 3, d4 = s & 7;
            float4 va = *(const float4*)&cb[(size_t)(i0 + m) * DIM + dc + d4 * 4];
            As[d4 * 4 + 0][m] = va.x; As[d4 * 4 + 1][m] = va.y;
            As[d4 * 4 + 2][m] = va.z; As[d4 * 4 + 3][m] = va.w;
            float4 vb = *(const float4*)&cb[(size_t)(j0 + m) * DIM + dc + d4 * 4];
            Bs[d4 * 4 + 0][m] = vb.x; Bs[d4 * 4 + 1][m] = vb.y;
            Bs[d4 * 4 + 2][m] = vb.z; Bs[d4 * 4 + 3][m] = vb.w;
        }
        __syncthreads();
#pragma unroll 8
        for (int dd = 0; dd < 32; dd++) {
            float4 a0 = *(const float4*)&As[dd][ty * 8];
            float4 a1 = *(const float4*)&As[dd][ty * 8 + 4];
            ulonglong2 b01 = *(const ulonglong2*)&Bs[dd][tx * 8];
            ulonglong2 b23 = *(const ulonglong2*)&Bs[dd][tx * 8 + 4];
            ull bp[4] = {b01.x, b01.y, b23.x, b23.y};
            float ar[8] = {a0.x, a0.y, a0.z, a0.w, a1.x, a1.y, a1.z, a1.w};
#pragma unroll
            for (int r = 0; r < 8; r++) {
                ull ap = pack2(ar[r], ar[r]);
#pragma unroll
                for (int p = 0; p < 4; p++) ffma2(acc2[r][p], ap, bp[p]);
            }
        }
        __syncthreads();
    }

    float sqi[8], sqj[8];
#pragma unroll
    for (int r = 0; r < 8; r++) sqi[r] = g_sq[i0 + ty * 8 + r];
#pragma unroll
    for (int j = 0; j < 8; j++) sqj[j] = g_sq[j0 + tx * 8 + j];

    float lsum = 0.f, lmin = INFINITY;
#pragma unroll
    for (int r = 0; r < 8; r++) {
        int gi = i0 + ty * 8 + r;
#pragma unroll
        for (int p = 0; p < 4; p++) {
            float alo, ahi;
            unpack2(alo, ahi, acc2[r][p]);
            int gj = j0 + tx * 8 + 2 * p;
            float d2a = sqi[r] + sqj[2 * p]     - 2.f * alo;
            float d2b = sqi[r] + sqj[2 * p + 1] - 2.f * ahi;
            float da = sqrtf(fmaxf(d2a, 0.f));
            float db = sqrtf(fmaxf(d2b, 0.f));
            if (gi != gj)     { lsum += da; lmin = fminf(lmin, da); }
            if (gi != gj + 1) { lsum += db; lmin = fminf(lmin, db); }
        }
    }
    float w = (bi < bj) ? 2.f : 1.f;  // mirror blocks counted twice for the sum
    lsum *= w;

    int lane = tid & 31, wp = tid >> 5;
#pragma unroll
    for (int off = 16; off; off >>= 1) {
        lsum += __shfl_xor_sync(0xffffffffu, lsum, off);
        lmin = fminf(lmin, __shfl_xor_sync(0xffffffffu, lmin, off));
    }
    if (lane == 0) { s_sum[wp] = lsum; s_min[wp] = lmin; }
    __syncthreads();
    if (tid == 0) {
        float bs = 0.f, bm = INFINITY;
#pragma unroll
        for (int i = 0; i < 8; i++) { bs += s_sum[i]; bm = fminf(bm, s_min[i]); }
        atomicAdd(&g_pair_sum, (double)bs);
        atomicMin(&g_min_bits, __float_as_uint(bm));  // positive floats: uint order == float order
    }
}

// --------- gather quantized rows + loss + selected-cosine + counts + index output ---------
__global__ void gather_loss_kernel(const float* __restrict__ latent,
                                   const float* __restrict__ cb,
                                   float* __restrict__ out) {
    int n = blockIdx.x;
    int d = threadIdx.x;
    int ix = g_idx[n];
    float q = cb[(size_t)ix * DIM + d];
    out[(size_t)n * DIM + d] = q;
    float diff = latent[(size_t)n * DIM + d] - q;
    float s = diff * diff;
    float sc = g_LN[(size_t)n * DIM + d] * g_CN[(size_t)ix * DIM + d];
#pragma unroll
    for (int off = 16; off; off >>= 1) {
        s  += __shfl_xor_sync(0xffffffffu, s, off);
        sc += __shfl_xor_sync(0xffffffffu, sc, off);
    }
    __shared__ float sh[8];
    __shared__ float shc[8];
    int lane = d & 31, wp = d >> 5;
    if (lane == 0) { sh[wp] = s; shc[wp] = sc; }
    __syncthreads();
    if (d == 0) {
        float bs = 0.f, bc = 0.f;
#pragma unroll
        for (int i = 0; i < 8; i++) { bs += sh[i]; bc += shc[i]; }
        atomicAdd(&g_loss_sum, (double)bs);
        atomicAdd(&g_sel_sum, (double)bc);
        atomicAdd(&g_counts[ix], 1);
        out[OUT_IDX_OFF + n] = (float)ix;
    }
}

// ---------------- finalize scalars ----------------
__global__ void finalize_kernel(float* __restrict__ out) {
    __shared__ double sh[256];
    int t = threadIdx.x;
    double s = 0.0;
    for (int k = t; k < K_CB; k += 256) {
        double p = (double)g_counts[k] / (double)N_TOK;
        s += p * log(p + 1e-10);
    }
    sh[t] = s;
    __syncthreads();
    for (int off = 128; off; off >>= 1) {
        if (t < off) sh[t] += sh[t + off];
        __syncthreads();
    }
    if (t == 0) {
        double S = sh[0];
        double X = g_loss_sum / (double)Q_ELEMS;
        float* o = out + OUT_SCALAR_OFF;
        o[0] = (float)(0.25 * X);                         // commitment_loss
        o[1] = (float)X;                                  // codebook_loss
        o[2] = (float)exp(-S);                            // perplexity
        o[3] = (float)(g_sel_sum / (double)N_TOK);        // selected_cosine_sim
        o[4] = (float)(g_pair_sum / ((double)K_CB * (K_CB - 1)));  // avg_euclidean
        o[5] = __uint_as_float(g_min_bits);               // min_euclidean
    }
}

extern "C" void kernel_launch(void* const* d_in, const int* in_sizes, int n_in,
                              void* d_out, int out_size) {
    const float* latent = (const float*)d_in[0];
    const float* cb     = (const float*)d_in[1];
    // defensive: handle swapped metadata order
    if (n_in >= 2 && in_sizes[0] == K_CB * DIM && in_sizes[1] == N_TOK * DIM) {
        const float* t = latent; latent = cb; cb = t;
    }
    float* out = (float*)d_out;

    const int COS_SMEM = 4 * T_BYTES;   // 73728 bytes dynamic
    cudaFuncSetAttribute(cosine_mma_kernel,
                         cudaFuncAttributeMaxDynamicSharedMemorySize, COS_SMEM);

    init_kernel<<<(K_CB + 255) / 256, 256>>>();
    prep_kernel<<<(N_TOK + K_CB) / 8, 256>>>(latent, cb);      // 1 warp/row
    cosine_mma_kernel<<<64 * NQ, 256, COS_SMEM>>>();           // 2048 CTAs, HMMA
    argmax_merge_kernel<<<N_TOK / 256, 256>>>();               // merge N-tiles + tie rule
    cdist_kernel<<<(32 * 33) / 2, 256>>>(cb);                  // 528 blocks, FFMA2
    gather_loss_kernel<<<N_TOK, 256>>>(latent, cb, out);
    finalize_kernel<<<1, 256>>>(out);
}

// round 16
// speedup vs baseline: 2.8126x; 1.3615x over previous
#include <cuda_runtime.h>
#include <cuda_bf16.h>
#include <math.h>
#include <stdint.h>

#define N_TOK 8192
#define K_CB  4096
#define DIM   256
#define KTOT  768                        // split-bf16 concat: [hi,hi,lo] x [hi,lo,hi]
#define NKC   12                         // 768 / 64
#define Q_ELEMS (N_TOK * DIM)            // 2097152
#define OUT_IDX_OFF Q_ELEMS              // indices start
#define OUT_SCALAR_OFF (Q_ELEMS + N_TOK) // 6 scalars start
#define TIE_TAU 1e-6f                    // near-tie window: resolve to lowest index
#define NQ 32                            // N-tiles of 128 in the cosine GEMM

#define APITCH 72                        // bf16 per SMEM row (64 data + 8 pad) = 36 words
#define TB (128 * APITCH * 2)            // 18432 bytes per tile stage
#define COS_SMEM (4 * TB)                // 73728: A[2] + B[2]

// ---------------- scratch (device globals; no allocations) ----------------
__device__ float g_LN[N_TOK * DIM];   // normalized latent rows (fp32, IEEE division)
__device__ float g_CN[K_CB * DIM];    // normalized codebook rows
__device__ __nv_bfloat16 g_LNcat[N_TOK * KTOT];  // normalized latent  [hi,hi,lo]
__device__ __nv_bfloat16 g_CNcat[K_CB * KTOT];   // normalized cb      [hi,lo,hi]
__device__ __nv_bfloat16 g_CBcatA[K_CB * KTOT];  // raw cb             [hi,hi,lo]
__device__ __nv_bfloat16 g_CBcatB[K_CB * KTOT];  // raw cb             [hi,lo,hi]
__device__ float g_sq[K_CB];          // raw ||codebook_k||^2
__device__ int   g_idx[N_TOK];
__device__ int   g_counts[K_CB];
__device__ float g_pv1[NQ * N_TOK];   // per-N-tile top-2 partials, layout [q][row]
__device__ float g_pv2[NQ * N_TOK];
__device__ int   g_pi1[NQ * N_TOK];
__device__ int   g_pi2[NQ * N_TOK];
__device__ double g_sel_sum;
__device__ double g_loss_sum;
__device__ double g_pair_sum;
__device__ unsigned int g_min_bits;

struct TopEnt { float v1, v2; int i1, i2; };

__device__ __forceinline__ void top2_ins(float& v1, int& i1, float& v2, int& i2,
                                         float w, int j) {
    if (w > v1 || (w == v1 && j < i1)) { v2 = v1; i2 = i1; v1 = w; i1 = j; }
    else if (w > v2 || (w == v2 && j < i2)) { v2 = w; i2 = j; }
}

#define CP16(dst, src) \
    asm volatile("cp.async.cg.shared.global [%0], [%1], 16;" :: "r"(dst), "l"(src))
#define CP_COMMIT() asm volatile("cp.async.commit_group;")
#define CP_WAIT1()  asm volatile("cp.async.wait_group 1;")
#define CP_WAIT0()  asm volatile("cp.async.wait_group 0;")

// ---------------- init: reset accumulators every launch ----------------
__global__ void init_kernel() {
    int t = blockIdx.x * blockDim.x + threadIdx.x;
    if (t < K_CB) g_counts[t] = 0;
    if (t == 0) {
        g_sel_sum  = 0.0;
        g_loss_sum = 0.0;
        g_pair_sum = 0.0;
        g_min_bits = 0x7f800000u;  // +inf
    }
}

// ------- row normalization + split-bf16 concat builds (one warp per row) -------
__global__ void prep_kernel(const float* __restrict__ latent,
                            const float* __restrict__ cb) {
    int warp = (blockIdx.x * blockDim.x + threadIdx.x) >> 5;
    int lane = threadIdx.x & 31;
    if (warp >= N_TOK + K_CB) return;
    bool is_lat = (warp < N_TOK);
    int row = is_lat ? warp : warp - N_TOK;
    const float* src = is_lat ? latent + (size_t)row * DIM : cb + (size_t)row * DIM;

    float v[8];
    float ss = 0.f;
#pragma unroll
    for (int i = 0; i < 8; i++) { v[i] = src[lane + 32 * i]; ss += v[i] * v[i]; }
#pragma unroll
    for (int o = 16; o; o >>= 1) ss += __shfl_xor_sync(0xffffffffu, ss, o);
    if (!is_lat && lane == 0) g_sq[row] = ss;                 // raw sum-of-squares
    float nrm = fmaxf(sqrtf(ss), 1e-12f);                     // clip(norm, 1e-12)

    if (is_lat) {
        float* dst = g_LN + (size_t)row * DIM;
        __nv_bfloat16* cat = g_LNcat + (size_t)row * KTOT;
#pragma unroll
        for (int i = 0; i < 8; i++) {
            int d = lane + 32 * i;
            float x = __fdiv_rn(v[i], nrm);
            dst[d] = x;
            __nv_bfloat16 h = __float2bfloat16_rn(x);
            __nv_bfloat16 l = __float2bfloat16_rn(x - __bfloat162float(h));
            cat[d] = h; cat[d + 256] = h; cat[d + 512] = l;   // A-order [hi,hi,lo]
        }
    } else {
        float* dst = g_CN + (size_t)row * DIM;
        __nv_bfloat16* catn = g_CNcat + (size_t)row * KTOT;
        __nv_bfloat16* cra  = g_CBcatA + (size_t)row * KTOT;
        __nv_bfloat16* crb  = g_CBcatB + (size_t)row * KTOT;
#pragma unroll
        for (int i = 0; i < 8; i++) {
            int d = lane + 32 * i;
            float x = __fdiv_rn(v[i], nrm);
            dst[d] = x;
            __nv_bfloat16 h = __float2bfloat16_rn(x);
            __nv_bfloat16 l = __float2bfloat16_rn(x - __bfloat162float(h));
            catn[d] = h; catn[d + 256] = l; catn[d + 512] = h;  // B-order [hi,lo,hi]
            float r = v[i];
            __nv_bfloat16 hr = __float2bfloat16_rn(r);
            __nv_bfloat16 lr = __float2bfloat16_rn(r - __bfloat162float(hr));
            cra[d] = hr; cra[d + 256] = hr; cra[d + 512] = lr;  // A-order
            crb[d] = hr; crb[d + 256] = lr; crb[d + 512] = hr;  // B-order
        }
    }
}

// ---------------- shared MMA mainloop (BM=BN=128, BK=64, K'=768, cp.async x2) ----------
__device__ __forceinline__ void mma_mainloop(
    const ushort* __restrict__ Acat, const ushort* __restrict__ Bcat,
    int m0, int n0, char* smem, uint32_t sbase,
    int tid, int wm, int wn, int tq, int tr, float acc[4][4][4]) {

#pragma unroll
    for (int mi = 0; mi < 4; mi++)
#pragma unroll
        for (int ni = 0; ni < 4; ni++)
#pragma unroll
            for (int c = 0; c < 4; c++) acc[mi][ni][c] = 0.f;

    // stage offsets: A: st*TB, B: 2*TB + st*TB
    auto issue = [&](int kc, int st) {
        int dc = kc * 64;
#pragma unroll
        for (int i = 0; i < 4; i++) {
            int s = tid + i * 256;             // 1024 slots of 8 bf16
            int m = s >> 3, c8 = (s & 7) * 8;
            uint32_t so = (uint32_t)((m * APITCH + c8) * 2);
            CP16(sbase + st * TB + so, (const char*)&Acat[(size_t)(m0 + m) * KTOT + dc + c8]);
            CP16(sbase + 2 * TB + st * TB + so, (const char*)&Bcat[(size_t)(n0 + m) * KTOT + dc + c8]);
        }
        CP_COMMIT();
    };

    issue(0, 0);
    for (int kc = 0; kc < NKC; kc++) {
        int st = kc & 1;
        if (kc + 1 < NKC) { issue(kc + 1, st ^ 1); CP_WAIT1(); }
        else              { CP_WAIT0(); }
        __syncthreads();
        const uint32_t* A = (const uint32_t*)(smem + st * TB);
        const uint32_t* B = (const uint32_t*)(smem + 2 * TB + st * TB);
#pragma unroll
        for (int ks = 0; ks < 4; ks++) {
            uint32_t a[4][4];
#pragma unroll
            for (int mi = 0; mi < 4; mi++) {
                int w = (wm * 64 + mi * 16 + tq) * 36 + ks * 8 + tr;
                a[mi][0] = A[w];
                a[mi][1] = A[w + 8 * 36];
                a[mi][2] = A[w + 4];
                a[mi][3] = A[w + 8 * 36 + 4];
            }
#pragma unroll
            for (int ni = 0; ni < 4; ni++) {
                int w = (wn * 32 + ni * 8 + tq) * 36 + ks * 8 + tr;
                uint32_t b0 = B[w], b1 = B[w + 4];
#pragma unroll
                for (int mi = 0; mi < 4; mi++) {
                    asm("mma.sync.aligned.m16n8k16.row.col.f32.bf16.bf16.f32 "
                        "{%0,%1,%2,%3}, {%4,%5,%6,%7}, {%8,%9}, {%0,%1,%2,%3};"
                        : "+f"(acc[mi][ni][0]), "+f"(acc[mi][ni][1]),
                          "+f"(acc[mi][ni][2]), "+f"(acc[mi][ni][3])
                        : "r"(a[mi][0]), "r"(a[mi][1]), "r"(a[mi][2]), "r"(a[mi][3]),
                          "r"(b0), "r"(b1));
                }
            }
        }
        __syncthreads();
    }
}

// ---- GEMM 1: cosine, single bf16 GEMM K'=768, fused top-2 ----
__global__ __launch_bounds__(256) void cosine_mma_kernel() {
    extern __shared__ __align__(16) char smem[];
    uint32_t sbase = (uint32_t)__cvta_generic_to_shared(smem);
    int tid = threadIdx.x;
    int wid = tid >> 5, lane = tid & 31;
    int wm = wid >> 2, wn = wid & 3;
    int tq = lane >> 2, tr = lane & 3;
    int nt = blockIdx.x & 31, mt = blockIdx.x >> 5;
    int m0 = mt * 128, n0 = nt * 128;

    float acc[4][4][4];
    mma_mainloop((const ushort*)g_LNcat, (const ushort*)g_CNcat,
                 m0, n0, smem, sbase, tid, wm, wn, tq, tr, acc);

    // epilogue: lane rows (wm*64+mi*16+tq+8h), cols (wn*32+ni*8+tr*2+{0,1})
    TopEnt* ebuf = (TopEnt*)smem;   // 512 entries, 8KB (tiles dead)
#pragma unroll
    for (int mi = 0; mi < 4; mi++)
#pragma unroll
        for (int h = 0; h < 2; h++) {
            float v1 = -INFINITY, v2 = -INFINITY;
            int i1 = 0, i2 = 0;
#pragma unroll
            for (int ni = 0; ni < 4; ni++) {   // ascending cols within lane
                int col = n0 + wn * 32 + ni * 8 + tr * 2;
                top2_ins(v1, i1, v2, i2, acc[mi][ni][h * 2], col);
                top2_ins(v1, i1, v2, i2, acc[mi][ni][h * 2 + 1], col + 1);
            }
#pragma unroll
            for (int off = 1; off <= 2; off <<= 1) {   // quad merge (same rows)
                float w1 = __shfl_xor_sync(0xffffffffu, v1, off);
                int   j1 = __shfl_xor_sync(0xffffffffu, i1, off);
                float w2 = __shfl_xor_sync(0xffffffffu, v2, off);
                int   j2 = __shfl_xor_sync(0xffffffffu, i2, off);
                top2_ins(v1, i1, v2, i2, w1, j1);
                top2_ins(v1, i1, v2, i2, w2, j2);
            }
            if (tr == 0) {
                int rit = wm * 64 + mi * 16 + tq + h * 8;
                TopEnt e; e.v1 = v1; e.v2 = v2; e.i1 = i1; e.i2 = i2;
                ebuf[rit * 4 + wn] = e;
            }
        }
    __syncthreads();
    if (tid < 128) {
        float v1 = -INFINITY, v2 = -INFINITY;
        int i1 = 0, i2 = 0;
#pragma unroll
        for (int w = 0; w < 4; w++) {   // ascending col ranges
            TopEnt e = ebuf[tid * 4 + w];
            top2_ins(v1, i1, v2, i2, e.v1, e.i1);
            top2_ins(v1, i1, v2, i2, e.v2, e.i2);
        }
        int o = nt * N_TOK + (m0 + tid);   // [q][row] layout: coalesced here and in merge
        g_pv1[o] = v1; g_pi1[o] = i1;
        g_pv2[o] = v2; g_pi2[o] = i2;
    }
}

// ---------------- merge per-N-tile top-2 partials + tie rule ----------------
__global__ void argmax_merge_kernel() {
    int row = blockIdx.x * blockDim.x + threadIdx.x;
    if (row >= N_TOK) return;
    float v1 = -INFINITY, v2 = -INFINITY;
    int i1 = 0, i2 = 0;
    for (int q = 0; q < NQ; q++) {      // ascending column ranges
        int o = q * N_TOK + row;        // coalesced
        top2_ins(v1, i1, v2, i2, g_pv1[o], g_pi1[o]);
        top2_ins(v1, i1, v2, i2, g_pv2[o], g_pi2[o]);
    }
    // near-tie: reference's softmax/argmax pipeline collapses sub-ulp gaps and
    // jnp.argmax resolves ties to the LOWEST index — emulate that.
    g_idx[row] = (v1 - v2 < TIE_TAU) ? min(i1, i2) : i1;
}

// ---- GEMM 2: codebook pairwise distances via HMMA split-bf16 (upper block-triangle) ----
__global__ __launch_bounds__(256) void cdist_kernel() {
    extern __shared__ __align__(16) char smem[];
    __shared__ float s_sum[8];
    __shared__ float s_min[8];
    uint32_t sbase = (uint32_t)__cvta_generic_to_shared(smem);
    int tid = threadIdx.x;
    int wid = tid >> 5, lane = tid & 31;
    int wm = wid >> 2, wn = wid & 3;
    int tq = lane >> 2, tr = lane & 3;

    int rem = blockIdx.x, bi = 0;
    while (rem >= 32 - bi) { rem -= 32 - bi; bi++; }
    int bj = bi + rem;
    int i0 = bi * 128, j0 = bj * 128;

    float acc[4][4][4];
    mma_mainloop((const ushort*)g_CBcatA, (const ushort*)g_CBcatB,
                 i0, j0, smem, sbase, tid, wm, wn, tq, tr, acc);

    float sqi[8], sqj[8];
#pragma unroll
    for (int mi = 0; mi < 4; mi++)
#pragma unroll
        for (int h = 0; h < 2; h++)
            sqi[mi * 2 + h] = g_sq[i0 + wm * 64 + mi * 16 + tq + 8 * h];
#pragma unroll
    for (int ni = 0; ni < 4; ni++)
#pragma unroll
        for (int e = 0; e < 2; e++)
            sqj[ni * 2 + e] = g_sq[j0 + wn * 32 + ni * 8 + tr * 2 + e];

    float lsum = 0.f, lmin = INFINITY;
#pragma unroll
    for (int mi = 0; mi < 4; mi++)
#pragma unroll
        for (int h = 0; h < 2; h++) {
            int gi = i0 + wm * 64 + mi * 16 + tq + 8 * h;
#pragma unroll
            for (int ni = 0; ni < 4; ni++)
#pragma unroll
                for (int e = 0; e < 2; e++) {
                    int gj = j0 + wn * 32 + ni * 8 + tr * 2 + e;
                    float d2 = sqi[mi * 2 + h] + sqj[ni * 2 + e]
                             - 2.f * acc[mi][ni][h * 2 + e];
                    float dd = sqrtf(fmaxf(d2, 0.f));
                    if (gi != gj) { lsum += dd; lmin = fminf(lmin, dd); }
                }
        }
    float w = (bi < bj) ? 2.f : 1.f;  // mirror blocks counted twice for the sum
    lsum *= w;

#pragma unroll
    for (int off = 16; off; off >>= 1) {
        lsum += __shfl_xor_sync(0xffffffffu, lsum, off);
        lmin = fminf(lmin, __shfl_xor_sync(0xffffffffu, lmin, off));
    }
    if (lane == 0) { s_sum[wid] = lsum; s_min[wid] = lmin; }
    __syncthreads();
    if (tid == 0) {
        float bs = 0.f, bm = INFINITY;
#pragma unroll
        for (int i = 0; i < 8; i++) { bs += s_sum[i]; bm = fminf(bm, s_min[i]); }
        atomicAdd(&g_pair_sum, (double)bs);
        atomicMin(&g_min_bits, __float_as_uint(bm));  // positive floats: uint order == float order
    }
}

// --------- gather quantized rows + loss + selected-cosine + counts + index output ---------
__global__ void gather_loss_kernel(const float* __restrict__ latent,
                                   const float* __restrict__ cb,
                                   float* __restrict__ out) {
    int n = blockIdx.x;
    int d = threadIdx.x;
    int ix = g_idx[n];
    float q = cb[(size_t)ix * DIM + d];
    out[(size_t)n * DIM + d] = q;
    float diff = latent[(size_t)n * DIM + d] - q;
    float s = diff * diff;
    float sc = g_LN[(size_t)n * DIM + d] * g_CN[(size_t)ix * DIM + d];
#pragma unroll
    for (int off = 16; off; off >>= 1) {
        s  += __shfl_xor_sync(0xffffffffu, s, off);
        sc += __shfl_xor_sync(0xffffffffu, sc, off);
    }
    __shared__ float sh[8];
    __shared__ float shc[8];
    int lane = d & 31, wp = d >> 5;
    if (lane == 0) { sh[wp] = s; shc[wp] = sc; }
    __syncthreads();
    if (d == 0) {
        float bs = 0.f, bc = 0.f;
#pragma unroll
        for (int i = 0; i < 8; i++) { bs += sh[i]; bc += shc[i]; }
        atomicAdd(&g_loss_sum, (double)bs);
        atomicAdd(&g_sel_sum, (double)bc);
        atomicAdd(&g_counts[ix], 1);
        out[OUT_IDX_OFF + n] = (float)ix;
    }
}

// ---------------- finalize scalars ----------------
__global__ void finalize_kernel(float* __restrict__ out) {
    __shared__ double sh[256];
    int t = threadIdx.x;
    double s = 0.0;
    for (int k = t; k < K_CB; k += 256) {
        double p = (double)g_counts[k] / (double)N_TOK;
        s += p * log(p + 1e-10);
    }
    sh[t] = s;
    __syncthreads();
    for (int off = 128; off; off >>= 1) {
        if (t < off) sh[t] += sh[t + off];
        __syncthreads();
    }
    if (t == 0) {
        double S = sh[0];
        double X = g_loss_sum / (double)Q_ELEMS;
        float* o = out + OUT_SCALAR_OFF;
        o[0] = (float)(0.25 * X);                         // commitment_loss
        o[1] = (float)X;                                  // codebook_loss
        o[2] = (float)exp(-S);                            // perplexity
        o[3] = (float)(g_sel_sum / (double)N_TOK);        // selected_cosine_sim
        o[4] = (float)(g_pair_sum / ((double)K_CB * (K_CB - 1)));  // avg_euclidean
        o[5] = __uint_as_float(g_min_bits);               // min_euclidean
    }
}

extern "C" void kernel_launch(void* const* d_in, const int* in_sizes, int n_in,
                              void* d_out, int out_size) {
    const float* latent = (const float*)d_in[0];
    const float* cb     = (const float*)d_in[1];
    // defensive: handle swapped metadata order
    if (n_in >= 2 && in_sizes[0] == K_CB * DIM && in_sizes[1] == N_TOK * DIM) {
        const float* t = latent; latent = cb; cb = t;
    }
    float* out = (float*)d_out;

    cudaFuncSetAttribute(cosine_mma_kernel,
                         cudaFuncAttributeMaxDynamicSharedMemorySize, COS_SMEM);
    cudaFuncSetAttribute(cdist_kernel,
                         cudaFuncAttributeMaxDynamicSharedMemorySize, COS_SMEM);

    init_kernel<<<(K_CB + 255) / 256, 256>>>();
    prep_kernel<<<(N_TOK + K_CB) / 8, 256>>>(latent, cb);      // 1 warp/row
    cosine_mma_kernel<<<64 * NQ, 256, COS_SMEM>>>();           // 2048 CTAs, HMMA, piped
    argmax_merge_kernel<<<N_TOK / 256, 256>>>();               // coalesced merge + tie rule
    cdist_kernel<<<(32 * 33) / 2, 256, COS_SMEM>>>();          // 528 blocks, HMMA, piped
    gather_loss_kernel<<<N_TOK, 256>>>(latent, cb, out);
    finalize_kernel<<<1, 256>>>(out);
}

// round 17
// speedup vs baseline: 3.0565x; 1.0867x over previous
#include <cuda_runtime.h>
#include <cuda_bf16.h>
#include <math.h>
#include <stdint.h>

#define N_TOK 8192
#define K_CB  4096
#define DIM   256
#define KTOT  768                        // split-bf16 concat: [hi,hi,lo] x [hi,lo,hi]
#define NKC   12                         // 768 / 64
#define Q_ELEMS (N_TOK * DIM)            // 2097152
#define OUT_IDX_OFF Q_ELEMS              // indices start
#define OUT_SCALAR_OFF (Q_ELEMS + N_TOK) // 6 scalars start
#define TIE_TAU 1e-6f                    // near-tie window: resolve to lowest index
#define NQ 32                            // N-tiles of 128 in the cosine GEMM

#define APITCH 72                        // bf16 per SMEM row (64 data + 8 pad) = 36 words
#define TB (128 * APITCH * 2)            // 18432 bytes per tile stage
#define COS_SMEM (4 * TB)                // 73728: A[2] + B[2]

// ---------------- scratch (device globals; no allocations) ----------------
__device__ float g_LN[N_TOK * DIM];   // normalized latent rows (fp32, IEEE division)
__device__ float g_CN[K_CB * DIM];    // normalized codebook rows
__device__ __nv_bfloat16 g_LNcat[N_TOK * KTOT];  // normalized latent  [hi,hi,lo]
__device__ __nv_bfloat16 g_CNcat[K_CB * KTOT];   // normalized cb      [hi,lo,hi]
__device__ __nv_bfloat16 g_CBcatA[K_CB * KTOT];  // raw cb             [hi,hi,lo]
__device__ __nv_bfloat16 g_CBcatB[K_CB * KTOT];  // raw cb             [hi,lo,hi]
__device__ float g_sq[K_CB];          // raw ||codebook_k||^2
__device__ int   g_idx[N_TOK];
__device__ int   g_counts[K_CB];
__device__ float g_pv1[NQ * N_TOK];   // per-N-tile top-2 partials, layout [q][row]
__device__ float g_pv2[NQ * N_TOK];
__device__ int   g_pi1[NQ * N_TOK];
__device__ int   g_pi2[NQ * N_TOK];
__device__ double g_sel_sum;
__device__ double g_loss_sum;
__device__ double g_pair_sum;
__device__ unsigned int g_min_bits;

struct TopEnt { float v1, v2; int i1, i2; };

__device__ __forceinline__ void top2_ins(float& v1, int& i1, float& v2, int& i2,
                                         float w, int j) {
    if (w > v1 || (w == v1 && j < i1)) { v2 = v1; i2 = i1; v1 = w; i1 = j; }
    else if (w > v2 || (w == v2 && j < i2)) { v2 = w; i2 = j; }
}

#define CP16(dst, src) \
    asm volatile("cp.async.cg.shared.global [%0], [%1], 16;" :: "r"(dst), "l"(src))
#define CP_COMMIT() asm volatile("cp.async.commit_group;")
#define CP_WAIT1()  asm volatile("cp.async.wait_group 1;")
#define CP_WAIT0()  asm volatile("cp.async.wait_group 0;")
#define LDSM_X4(rg, addr) \
    asm volatile("ldmatrix.sync.aligned.m8n8.x4.shared.b16 {%0,%1,%2,%3}, [%4];" \
        : "=r"((rg)[0]), "=r"((rg)[1]), "=r"((rg)[2]), "=r"((rg)[3]) : "r"(addr))

// ---------------- init: reset accumulators every launch ----------------
__global__ void init_kernel() {
    int t = blockIdx.x * blockDim.x + threadIdx.x;
    if (t < K_CB) g_counts[t] = 0;
    if (t == 0) {
        g_sel_sum  = 0.0;
        g_loss_sum = 0.0;
        g_pair_sum = 0.0;
        g_min_bits = 0x7f800000u;  // +inf
    }
}

// ------- row normalization + split-bf16 concat builds (one warp per row) -------
__global__ void prep_kernel(const float* __restrict__ latent,
                            const float* __restrict__ cb) {
    int warp = (blockIdx.x * blockDim.x + threadIdx.x) >> 5;
    int lane = threadIdx.x & 31;
    if (warp >= N_TOK + K_CB) return;
    bool is_lat = (warp < N_TOK);
    int row = is_lat ? warp : warp - N_TOK;
    const float* src = is_lat ? latent + (size_t)row * DIM : cb + (size_t)row * DIM;

    float v[8];
    float ss = 0.f;
#pragma unroll
    for (int i = 0; i < 8; i++) { v[i] = src[lane + 32 * i]; ss += v[i] * v[i]; }
#pragma unroll
    for (int o = 16; o; o >>= 1) ss += __shfl_xor_sync(0xffffffffu, ss, o);
    if (!is_lat && lane == 0) g_sq[row] = ss;                 // raw sum-of-squares
    float nrm = fmaxf(sqrtf(ss), 1e-12f);                     // clip(norm, 1e-12)

    if (is_lat) {
        float* dst = g_LN + (size_t)row * DIM;
        __nv_bfloat16* cat = g_LNcat + (size_t)row * KTOT;
#pragma unroll
        for (int i = 0; i < 8; i++) {
            int d = lane + 32 * i;
            float x = __fdiv_rn(v[i], nrm);
            dst[d] = x;
            __nv_bfloat16 h = __float2bfloat16_rn(x);
            __nv_bfloat16 l = __float2bfloat16_rn(x - __bfloat162float(h));
            cat[d] = h; cat[d + 256] = h; cat[d + 512] = l;   // A-order [hi,hi,lo]
        }
    } else {
        float* dst = g_CN + (size_t)row * DIM;
        __nv_bfloat16* catn = g_CNcat + (size_t)row * KTOT;
        __nv_bfloat16* cra  = g_CBcatA + (size_t)row * KTOT;
        __nv_bfloat16* crb  = g_CBcatB + (size_t)row * KTOT;
#pragma unroll
        for (int i = 0; i < 8; i++) {
            int d = lane + 32 * i;
            float x = __fdiv_rn(v[i], nrm);
            dst[d] = x;
            __nv_bfloat16 h = __float2bfloat16_rn(x);
            __nv_bfloat16 l = __float2bfloat16_rn(x - __bfloat162float(h));
            catn[d] = h; catn[d + 256] = l; catn[d + 512] = h;  // B-order [hi,lo,hi]
            float r = v[i];
            __nv_bfloat16 hr = __float2bfloat16_rn(r);
            __nv_bfloat16 lr = __float2bfloat16_rn(r - __bfloat162float(hr));
            cra[d] = hr; cra[d + 256] = hr; cra[d + 512] = lr;  // A-order
            crb[d] = hr; crb[d + 256] = lr; crb[d + 512] = hr;  // B-order
        }
    }
}

// ---------------- shared MMA mainloop (BM=BN=128, BK=64, K'=768, cp.async x2) ----------
// Fragment loads via ldmatrix.x4 (bit-identical values, 4x fewer shared-load instrs).
__device__ __forceinline__ void mma_mainloop(
    const ushort* __restrict__ Acat, const ushort* __restrict__ Bcat,
    int m0, int n0, char* smem, uint32_t sbase,
    int tid, int wm, int wn, float acc[4][4][4]) {

#pragma unroll
    for (int mi = 0; mi < 4; mi++)
#pragma unroll
        for (int ni = 0; ni < 4; ni++)
#pragma unroll
            for (int c = 0; c < 4; c++) acc[mi][ni][c] = 0.f;

    int lane = tid & 31;
    int lr = lane & 7, lt = lane >> 3;   // ldmatrix: row within tile, tile index
    // A tiles: (lt&1) -> +8 rows, (lt>>1) -> +4 words (col halves)
    uint32_t aoff = (uint32_t)(((wm * 64 + (lt & 1) * 8 + lr) * 36 + (lt >> 1) * 4) * 4);
    // B tiles: (lt>>1) -> +8 rows (ni within pair), (lt&1) -> +4 words
    uint32_t boff = (uint32_t)(((wn * 32 + (lt >> 1) * 8 + lr) * 36 + (lt & 1) * 4) * 4);

    auto issue = [&](int kc, int st) {
        int dc = kc * 64;
#pragma unroll
        for (int i = 0; i < 4; i++) {
            int s = tid + i * 256;             // 1024 slots of 8 bf16
            int m = s >> 3, c8 = (s & 7) * 8;
            uint32_t so = (uint32_t)((m * APITCH + c8) * 2);
            CP16(sbase + st * TB + so, (const char*)&Acat[(size_t)(m0 + m) * KTOT + dc + c8]);
            CP16(sbase + 2 * TB + st * TB + so, (const char*)&Bcat[(size_t)(n0 + m) * KTOT + dc + c8]);
        }
        CP_COMMIT();
    };

    issue(0, 0);
    for (int kc = 0; kc < NKC; kc++) {
        int st = kc & 1;
        if (kc + 1 < NKC) { issue(kc + 1, st ^ 1); CP_WAIT1(); }
        else              { CP_WAIT0(); }
        __syncthreads();
        uint32_t Ab = sbase + st * TB + aoff;
        uint32_t Bb = sbase + 2 * TB + st * TB + boff;
#pragma unroll
        for (int ks = 0; ks < 4; ks++) {
            uint32_t a[4][4];
#pragma unroll
            for (int mi = 0; mi < 4; mi++)
                LDSM_X4(a[mi], Ab + (uint32_t)((mi * 576 + ks * 8) * 4));
            uint32_t b[2][4];
#pragma unroll
            for (int p = 0; p < 2; p++)
                LDSM_X4(b[p], Bb + (uint32_t)((p * 576 + ks * 8) * 4));
#pragma unroll
            for (int ni = 0; ni < 4; ni++) {
                uint32_t b0 = b[ni >> 1][(ni & 1) * 2];
                uint32_t b1 = b[ni >> 1][(ni & 1) * 2 + 1];
#pragma unroll
                for (int mi = 0; mi < 4; mi++) {
                    asm("mma.sync.aligned.m16n8k16.row.col.f32.bf16.bf16.f32 "
                        "{%0,%1,%2,%3}, {%4,%5,%6,%7}, {%8,%9}, {%0,%1,%2,%3};"
                        : "+f"(acc[mi][ni][0]), "+f"(acc[mi][ni][1]),
                          "+f"(acc[mi][ni][2]), "+f"(acc[mi][ni][3])
                        : "r"(a[mi][0]), "r"(a[mi][1]), "r"(a[mi][2]), "r"(a[mi][3]),
                          "r"(b0), "r"(b1));
                }
            }
        }
        __syncthreads();
    }
}

// ---- GEMM 1: cosine, single bf16 GEMM K'=768, fused top-2 ----
__global__ __launch_bounds__(256) void cosine_mma_kernel() {
    extern __shared__ __align__(16) char smem[];
    uint32_t sbase = (uint32_t)__cvta_generic_to_shared(smem);
    int tid = threadIdx.x;
    int wid = tid >> 5, lane = tid & 31;
    int wm = wid >> 2, wn = wid & 3;
    int tq = lane >> 2, tr = lane & 3;
    int nt = blockIdx.x & 31, mt = blockIdx.x >> 5;
    int m0 = mt * 128, n0 = nt * 128;

    float acc[4][4][4];
    mma_mainloop((const ushort*)g_LNcat, (const ushort*)g_CNcat,
                 m0, n0, smem, sbase, tid, wm, wn, acc);

    // epilogue: lane rows (wm*64+mi*16+tq+8h), cols (wn*32+ni*8+tr*2+{0,1})
    TopEnt* ebuf = (TopEnt*)smem;   // 512 entries, 8KB (tiles dead)
#pragma unroll
    for (int mi = 0; mi < 4; mi++)
#pragma unroll
        for (int h = 0; h < 2; h++) {
            float v1 = -INFINITY, v2 = -INFINITY;
            int i1 = 0, i2 = 0;
#pragma unroll
            for (int ni = 0; ni < 4; ni++) {   // ascending cols within lane
                int col = n0 + wn * 32 + ni * 8 + tr * 2;
                top2_ins(v1, i1, v2, i2, acc[mi][ni][h * 2], col);
                top2_ins(v1, i1, v2, i2, acc[mi][ni][h * 2 + 1], col + 1);
            }
#pragma unroll
            for (int off = 1; off <= 2; off <<= 1) {   // quad merge (same rows)
                float w1 = __shfl_xor_sync(0xffffffffu, v1, off);
                int   j1 = __shfl_xor_sync(0xffffffffu, i1, off);
                float w2 = __shfl_xor_sync(0xffffffffu, v2, off);
                int   j2 = __shfl_xor_sync(0xffffffffu, i2, off);
                top2_ins(v1, i1, v2, i2, w1, j1);
                top2_ins(v1, i1, v2, i2, w2, j2);
            }
            if (tr == 0) {
                int rit = wm * 64 + mi * 16 + tq + h * 8;
                TopEnt e; e.v1 = v1; e.v2 = v2; e.i1 = i1; e.i2 = i2;
                ebuf[rit * 4 + wn] = e;
            }
        }
    __syncthreads();
    if (tid < 128) {
        float v1 = -INFINITY, v2 = -INFINITY;
        int i1 = 0, i2 = 0;
#pragma unroll
        for (int w = 0; w < 4; w++) {   // ascending col ranges
            TopEnt e = ebuf[tid * 4 + w];
            top2_ins(v1, i1, v2, i2, e.v1, e.i1);
            top2_ins(v1, i1, v2, i2, e.v2, e.i2);
        }
        int o = nt * N_TOK + (m0 + tid);   // [q][row] layout
        g_pv1[o] = v1; g_pi1[o] = i1;
        g_pv2[o] = v2; g_pi2[o] = i2;
    }
}

// -------- merge per-N-tile top-2 partials + tie rule (8 threads per row) --------
__global__ void argmax_merge_kernel() {
    int gid = blockIdx.x * blockDim.x + threadIdx.x;
    int row = gid >> 3;          // 8 threads per row
    int sub = gid & 7;           // each handles 4 consecutive q's (ascending)
    if (row >= N_TOK) return;
    float v1 = -INFINITY, v2 = -INFINITY;
    int i1 = 0, i2 = 0;
#pragma unroll
    for (int qq = 0; qq < 4; qq++) {
        int o = (sub * 4 + qq) * N_TOK + row;
        top2_ins(v1, i1, v2, i2, g_pv1[o], g_pi1[o]);
        top2_ins(v1, i1, v2, i2, g_pv2[o], g_pi2[o]);
    }
    // merge the 8 per-thread top-2 sets (comparator is order-independent)
#pragma unroll
    for (int off = 1; off <= 4; off <<= 1) {
        float w1 = __shfl_xor_sync(0xffffffffu, v1, off);
        int   j1 = __shfl_xor_sync(0xffffffffu, i1, off);
        float w2 = __shfl_xor_sync(0xffffffffu, v2, off);
        int   j2 = __shfl_xor_sync(0xffffffffu, i2, off);
        top2_ins(v1, i1, v2, i2, w1, j1);
        top2_ins(v1, i1, v2, i2, w2, j2);
    }
    if (sub == 0) {
        // near-tie: reference's softmax/argmax pipeline collapses sub-ulp gaps and
        // jnp.argmax resolves ties to the LOWEST index — emulate that.
        g_idx[row] = (v1 - v2 < TIE_TAU) ? min(i1, i2) : i1;
    }
}

// ---- GEMM 2: codebook pairwise distances via HMMA split-bf16 (upper block-triangle) ----
__global__ __launch_bounds__(256) void cdist_kernel() {
    extern __shared__ __align__(16) char smem[];
    __shared__ float s_sum[8];
    __shared__ float s_min[8];
    uint32_t sbase = (uint32_t)__cvta_generic_to_shared(smem);
    int tid = threadIdx.x;
    int wid = tid >> 5, lane = tid & 31;
    int wm = wid >> 2, wn = wid & 3;
    int tq = lane >> 2, tr = lane & 3;

    int rem = blockIdx.x, bi = 0;
    while (rem >= 32 - bi) { rem -= 32 - bi; bi++; }
    int bj = bi + rem;
    int i0 = bi * 128, j0 = bj * 128;

    float acc[4][4][4];
    mma_mainloop((const ushort*)g_CBcatA, (const ushort*)g_CBcatB,
                 i0, j0, smem, sbase, tid, wm, wn, acc);

    float sqi[8], sqj[8];
#pragma unroll
    for (int mi = 0; mi < 4; mi++)
#pragma unroll
        for (int h = 0; h < 2; h++)
            sqi[mi * 2 + h] = g_sq[i0 + wm * 64 + mi * 16 + tq + 8 * h];
#pragma unroll
    for (int ni = 0; ni < 4; ni++)
#pragma unroll
        for (int e = 0; e < 2; e++)
            sqj[ni * 2 + e] = g_sq[j0 + wn * 32 + ni * 8 + tr * 2 + e];

    float lsum = 0.f, lmin = INFINITY;
#pragma unroll
    for (int mi = 0; mi < 4; mi++)
#pragma unroll
        for (int h = 0; h < 2; h++) {
            int gi = i0 + wm * 64 + mi * 16 + tq + 8 * h;
#pragma unroll
            for (int ni = 0; ni < 4; ni++)
#pragma unroll
                for (int e = 0; e < 2; e++) {
                    int gj = j0 + wn * 32 + ni * 8 + tr * 2 + e;
                    float d2 = sqi[mi * 2 + h] + sqj[ni * 2 + e]
                             - 2.f * acc[mi][ni][h * 2 + e];
                    float dd = sqrtf(fmaxf(d2, 0.f));
                    if (gi != gj) { lsum += dd; lmin = fminf(lmin, dd); }
                }
        }
    float w = (bi < bj) ? 2.f : 1.f;  // mirror blocks counted twice for the sum
    lsum *= w;

#pragma unroll
    for (int off = 16; off; off >>= 1) {
        lsum += __shfl_xor_sync(0xffffffffu, lsum, off);
        lmin = fminf(lmin, __shfl_xor_sync(0xffffffffu, lmin, off));
    }
    if (lane == 0) { s_sum[wid] = lsum; s_min[wid] = lmin; }
    __syncthreads();
    if (tid == 0) {
        float bs = 0.f, bm = INFINITY;
#pragma unroll
        for (int i = 0; i < 8; i++) { bs += s_sum[i]; bm = fminf(bm, s_min[i]); }
        atomicAdd(&g_pair_sum, (double)bs);
        atomicMin(&g_min_bits, __float_as_uint(bm));  // positive floats: uint order == float order
    }
}

// --------- gather quantized rows + loss + selected-cosine + counts + index output ---------
__global__ void gather_loss_kernel(const float* __restrict__ latent,
                                   const float* __restrict__ cb,
                                   float* __restrict__ out) {
    int n = blockIdx.x;
    int d = threadIdx.x;
    int ix = g_idx[n];
    float q = cb[(size_t)ix * DIM + d];
    out[(size_t)n * DIM + d] = q;
    float diff = latent[(size_t)n * DIM + d] - q;
    float s = diff * diff;
    float sc = g_LN[(size_t)n * DIM + d] * g_CN[(size_t)ix * DIM + d];
#pragma unroll
    for (int off = 16; off; off >>= 1) {
        s  += __shfl_xor_sync(0xffffffffu, s, off);
        sc += __shfl_xor_sync(0xffffffffu, sc, off);
    }
    __shared__ float sh[8];
    __shared__ float shc[8];
    int lane = d & 31, wp = d >> 5;
    if (lane == 0) { sh[wp] = s; shc[wp] = sc; }
    __syncthreads();
    if (d == 0) {
        float bs = 0.f, bc = 0.f;
#pragma unroll
        for (int i = 0; i < 8; i++) { bs += sh[i]; bc += shc[i]; }
        atomicAdd(&g_loss_sum, (double)bs);
        atomicAdd(&g_sel_sum, (double)bc);
        atomicAdd(&g_counts[ix], 1);
        out[OUT_IDX_OFF + n] = (float)ix;
    }
}

// ---------------- finalize scalars ----------------
__global__ void finalize_kernel(float* __restrict__ out) {
    __shared__ double sh[256];
    int t = threadIdx.x;
    double s = 0.0;
    for (int k = t; k < K_CB; k += 256) {
        double p = (double)g_counts[k] / (double)N_TOK;
        s += p * log(p + 1e-10);
    }
    sh[t] = s;
    __syncthreads();
    for (int off = 128; off; off >>= 1) {
        if (t < off) sh[t] += sh[t + off];
        __syncthreads();
    }
    if (t == 0) {
        double S = sh[0];
        double X = g_loss_sum / (double)Q_ELEMS;
        float* o = out + OUT_SCALAR_OFF;
        o[0] = (float)(0.25 * X);                         // commitment_loss
        o[1] = (float)X;                                  // codebook_loss
        o[2] = (float)exp(-S);                            // perplexity
        o[3] = (float)(g_sel_sum / (double)N_TOK);        // selected_cosine_sim
        o[4] = (float)(g_pair_sum / ((double)K_CB * (K_CB - 1)));  // avg_euclidean
        o[5] = __uint_as_float(g_min_bits);               // min_euclidean
    }
}

extern "C" void kernel_launch(void* const* d_in, const int* in_sizes, int n_in,
                              void* d_out, int out_size) {
    const float* latent = (const float*)d_in[0];
    const float* cb     = (const float*)d_in[1];
    // defensive: handle swapped metadata order
    if (n_in >= 2 && in_sizes[0] == K_CB * DIM && in_sizes[1] == N_TOK * DIM) {
        const float* t = latent; latent = cb; cb = t;
    }
    float* out = (float*)d_out;

    cudaFuncSetAttribute(cosine_mma_kernel,
                         cudaFuncAttributeMaxDynamicSharedMemorySize, COS_SMEM);
    cudaFuncSetAttribute(cdist_kernel,
                         cudaFuncAttributeMaxDynamicSharedMemorySize, COS_SMEM);

    init_kernel<<<(K_CB + 255) / 256, 256>>>();
    prep_kernel<<<(N_TOK + K_CB) / 8, 256>>>(latent, cb);      // 1 warp/row
    cosine_mma_kernel<<<64 * NQ, 256, COS_SMEM>>>();           // 2048 CTAs, HMMA+ldmatrix
    argmax_merge_kernel<<<N_TOK * 8 / 256, 256>>>();           // 8 thr/row merge + tie rule
    cdist_kernel<<<(32 * 33) / 2, 256, COS_SMEM>>>();          // 528 blocks, HMMA+ldmatrix
    gather_loss_kernel<<<N_TOK, 256>>>(latent, cb, out);
    finalize_kernel<<<1, 256>>>(out);
}